// round 11
// baseline (speedup 1.0000x reference)
#include <cuda_runtime.h>
#include <cuda_bf16.h>
#include <cstdint>

#define T_STEPS 30
#define HID     1024
#define LAYERS  4
#define ZCOLS   4096
#define BH      (256 * HID)
#define NSTEPS  (T_STEPS * LAYERS)   // 120

#define KC          128               // bf16 k-elements per stage (2 SW128 panels)
#define NCHUNK      48                // 6 terms * (1024/128)
#define A_BYTES     16384             // 2 panels x (64 x 128B)
#define B_BYTES     32768             // 2 panels x (128 x 128B)
#define A_PANEL     8192
#define B_PANEL     16384
#define STAGE_BYTES (A_BYTES + B_BYTES)          // 49152
#define SMEM_BYTES  (3 * STAGE_BYTES)            // 147456
#define GRID_CTAS   128

// ---------------- scratch (__device__ globals) ----------------
__device__ __nv_bfloat16 g_w[2][LAYERS][2][ZCOLS * HID];
__device__ __nv_bfloat16 g_xh[T_STEPS * BH];
__device__ __nv_bfloat16 g_xl[T_STEPS * BH];
__device__ float         g_c[LAYERS][BH];
__device__ __nv_bfloat16 g_hh[LAYERS][2][BH];
__device__ __nv_bfloat16 g_hl[LAYERS][2][BH];
__device__ __nv_bfloat16 g_curh[2][BH];
__device__ __nv_bfloat16 g_curl[2][BH];
__device__ float         g_biasp[LAYERS][ZCOLS];
__device__ unsigned      g_bar;

// ---------------- helpers ----------------
__device__ __forceinline__ uint32_t smem_u32(const void* p) {
    uint32_t a;
    asm("{ .reg .u64 t; cvta.to.shared.u64 t, %1; cvt.u32.u64 %0, t; }" : "=r"(a) : "l"(p));
    return a;
}
__device__ __forceinline__ void cp16(uint32_t dst, const void* src) {
    asm volatile("cp.async.cg.shared.global [%0], [%1], 16;"
                 :: "r"(dst), "l"(__cvta_generic_to_global(src)) : "memory");
}
__device__ __forceinline__ uint32_t sw128(uint32_t off) {
    return off ^ ((off >> 3) & 0x70);
}
__device__ __forceinline__ void ldmat4(uint32_t addr, uint32_t& r0, uint32_t& r1,
                                       uint32_t& r2, uint32_t& r3) {
    asm volatile("ldmatrix.sync.aligned.m8n8.x4.shared.b16 {%0,%1,%2,%3}, [%4];"
                 : "=r"(r0), "=r"(r1), "=r"(r2), "=r"(r3) : "r"(addr));
}
__device__ __forceinline__ void mma_bf16(float& d0, float& d1, float& d2, float& d3,
                                         uint32_t a0, uint32_t a1, uint32_t a2, uint32_t a3,
                                         uint32_t b0, uint32_t b1) {
    asm volatile("mma.sync.aligned.m16n8k16.row.col.f32.bf16.bf16.f32 "
                 "{%0,%1,%2,%3},{%4,%5,%6,%7},{%8,%9},{%0,%1,%2,%3};"
                 : "+f"(d0), "+f"(d1), "+f"(d2), "+f"(d3)
                 : "r"(a0), "r"(a1), "r"(a2), "r"(a3), "r"(b0), "r"(b1));
}
__device__ __forceinline__ void split_bf(float x, uint32_t& hi, uint32_t& lo) {
    __nv_bfloat16 h = __float2bfloat16(x);
    __nv_bfloat16 l = __float2bfloat16(x - __bfloat162float(h));
    hi = (uint32_t)__bfloat16_as_ushort(h);
    lo = (uint32_t)__bfloat16_as_ushort(l);
}

struct Ptrs {
    const __nv_bfloat16 *ah, *al, *hhp, *hlp, *w1h, *w1l, *w2h, *w2l;
};
__device__ __forceinline__ void get_ptrs(int step, Ptrs& P) {
    int t = step >> 2, j = step & 3;
    P.ah  = (j == 0) ? g_xh + (size_t)t * BH : g_curh[j & 1];
    P.al  = (j == 0) ? g_xl + (size_t)t * BH : g_curl[j & 1];
    P.hhp = g_hh[j][t & 1];
    P.hlp = g_hl[j][t & 1];
    P.w1h = g_w[0][j][0]; P.w1l = g_w[0][j][1];
    P.w2h = g_w[1][j][0]; P.w2l = g_w[1][j][1];
}
__device__ __forceinline__ const __nv_bfloat16* selA(const Ptrs& P, int p) {
    return (p <= 1) ? P.ah : (p == 2) ? P.al : (p <= 4) ? P.hhp : P.hlp;
}
__device__ __forceinline__ const __nv_bfloat16* selB(const Ptrs& P, int p) {
    return (p == 0 || p == 2) ? P.w1h : (p == 1) ? P.w1l : (p == 4) ? P.w2l : P.w2h;
}

// ---------------- init kernels ----------------
__global__ void zero_state_kernel() {
    int i = blockIdx.x * blockDim.x + threadIdx.x;
    if (i == 0) g_bar = 0u;
    int nc = LAYERS * BH;
    int nh = LAYERS * 2 * BH / 2;
    if (i < nc) ((float*)g_c)[i] = 0.0f;
    if (i < nh) { ((uint32_t*)g_hh)[i] = 0u; ((uint32_t*)g_hl)[i] = 0u; }
}

__global__ void bias_perm_kernel(const float* __restrict__ bias) {
    int i = blockIdx.x * blockDim.x + threadIdx.x;
    if (i >= LAYERS * ZCOLS) return;
    int l = i >> 12, n = i & 4095;
    int np = 4 * (n & 1023) + (n >> 10);
    g_biasp[l][np] = bias[i];
}

__global__ void wsplit_kernel(const float* __restrict__ kern, const float* __restrict__ rec) {
    __shared__ float t[32][33];
    int mat = blockIdx.z >> 2;
    int l   = blockIdx.z & 3;
    const float* src = (mat ? rec : kern) + (size_t)l * HID * ZCOLS;
    int n0 = blockIdx.x * 32, k0 = blockIdx.y * 32;
    int tx = threadIdx.x, ty = threadIdx.y;
    #pragma unroll
    for (int i = 0; i < 4; i++)
        t[ty + i * 8][tx] = src[(size_t)(k0 + ty + i * 8) * ZCOLS + n0 + tx];
    __syncthreads();
    __nv_bfloat16* oh = g_w[mat][l][0];
    __nv_bfloat16* ol = g_w[mat][l][1];
    #pragma unroll
    for (int i = 0; i < 4; i++) {
        int nl = ty + i * 8;
        int n  = n0 + nl;
        int np = 4 * (n & 1023) + (n >> 10);
        float v = t[tx][nl];
        __nv_bfloat16 h = __float2bfloat16(v);
        oh[(size_t)np * HID + k0 + tx] = h;
        ol[(size_t)np * HID + k0 + tx] = __float2bfloat16(v - __bfloat162float(h));
    }
}

__global__ void xsplit_kernel(const float* __restrict__ x) {
    int i = blockIdx.x * blockDim.x + threadIdx.x;
    if (i >= T_STEPS * BH) return;
    float v = x[i];
    __nv_bfloat16 h = __float2bfloat16(v);
    g_xh[i] = h;
    g_xl[i] = __float2bfloat16(v - __bfloat162float(h));
}

// ---------------- persistent fused LSTM ----------------
__global__ __launch_bounds__(256, 1) void lstm_persistent_kernel(float* __restrict__ out)
{
    extern __shared__ char smem[];
    const uint32_t sb = smem_u32(smem);
    const int tid  = threadIdx.x;
    const int lane = tid & 31;
    const int wid  = tid >> 5;
    const int wm = wid >> 2;
    const int wn = wid & 3;
    const int blockN   = blockIdx.x * 128;
    const int blockRow = blockIdx.y * 64;

    // cp.async load maps
    const int ld_row = tid >> 3;           // 0..31
    const int ld_c16 = tid & 7;            // 0..7
    uint32_t aDst[2], bDst[4];
    #pragma unroll
    for (int r = 0; r < 2; r++)
        aDst[r] = sw128((uint32_t)((ld_row + r * 32) * 128 + ld_c16 * 16));
    #pragma unroll
    for (int r = 0; r < 4; r++)
        bDst[r] = A_BYTES + sw128((uint32_t)((ld_row + r * 32) * 128 + ld_c16 * 16));

    // ldmatrix base offsets (XOR (ks&3)*32; panel offset added at use)
    uint32_t aBase[2], bBase[2];
    {
        int mA = wm * 32 + (lane & 7) + ((lane >> 3) & 1) * 8;
        int kA = (lane >> 4) * 16;
        int nB = wn * 32 + (lane & 7) + ((lane >> 4) & 1) * 8;
        int kB = ((lane >> 3) & 1) * 16;
        #pragma unroll
        for (int mi = 0; mi < 2; mi++) {
            int row = mA + mi * 16;
            aBase[mi] = (uint32_t)(row * 128) + ((uint32_t)kA ^ ((uint32_t)(row & 7) * 16));
        }
        #pragma unroll
        for (int nh2 = 0; nh2 < 2; nh2++) {
            int row = nB + nh2 * 16;
            bBase[nh2] = A_BYTES + (uint32_t)(row * 128) + ((uint32_t)kB ^ ((uint32_t)(row & 7) * 16));
        }
    }

    auto loadA = [&](const Ptrs& P, int jc, int s) {
        int p = jc >> 3, k0 = (jc & 7) * KC;
        const __nv_bfloat16* As = selA(P, p);
        uint32_t base = sb + (uint32_t)s * STAGE_BYTES;
        #pragma unroll
        for (int pi = 0; pi < 2; pi++)
            #pragma unroll
            for (int r = 0; r < 2; r++)
                cp16(base + pi * A_PANEL + aDst[r],
                     As + (size_t)(blockRow + ld_row + r * 32) * HID + k0 + pi * 64 + ld_c16 * 8);
    };
    auto loadB = [&](const Ptrs& P, int jc, int s) {
        int p = jc >> 3, k0 = (jc & 7) * KC;
        const __nv_bfloat16* Bs = selB(P, p);
        uint32_t base = sb + (uint32_t)s * STAGE_BYTES;
        #pragma unroll
        for (int pi = 0; pi < 2; pi++)
            #pragma unroll
            for (int r = 0; r < 4; r++)
                cp16(base + pi * B_PANEL + bDst[r],
                     Bs + (size_t)(blockN + ld_row + r * 32) * HID + k0 + pi * 64 + ld_c16 * 8);
    };

    auto ldsm_ks = [&](uint32_t base, int ks, uint32_t a[2][4], uint32_t bt[2][4]) {
        uint32_t xk  = (uint32_t)((ks & 3) * 32);
        uint32_t pkA = (uint32_t)((ks >> 2) * A_PANEL);
        uint32_t pkB = (uint32_t)((ks >> 2) * B_PANEL);
        #pragma unroll
        for (int mi = 0; mi < 2; mi++)
            ldmat4(base + pkA + (aBase[mi] ^ xk), a[mi][0], a[mi][1], a[mi][2], a[mi][3]);
        #pragma unroll
        for (int nh2 = 0; nh2 < 2; nh2++)
            ldmat4(base + pkB + (bBase[nh2] ^ xk), bt[nh2][0], bt[nh2][1], bt[nh2][2], bt[nh2][3]);
    };

    // prologue: prefetch chunks 0,1 (B first — matches in-loop group order)
    Ptrs P;
    get_ptrs(0, P);
    loadB(P, 0, 0); asm volatile("cp.async.commit_group;" ::: "memory");
    loadB(P, 1, 1); asm volatile("cp.async.commit_group;" ::: "memory");
    loadA(P, 0, 0); asm volatile("cp.async.commit_group;" ::: "memory");
    loadA(P, 1, 1); asm volatile("cp.async.commit_group;" ::: "memory");

    #pragma unroll 1
    for (int step = 0; step < NSTEPS; step++) {
        const int t = step >> 2;
        const int j = step & 3;
        get_ptrs(step, P);

        float d[2][4][4];
        #pragma unroll
        for (int mi = 0; mi < 2; mi++)
            #pragma unroll
            for (int ni = 0; ni < 4; ni++)
                #pragma unroll
                for (int r = 0; r < 4; r++) d[mi][ni][r] = 0.0f;

        int s_cmp = 0, s_load = 2;
        #pragma unroll 1
        for (int i = 0; i < NCHUNK; i++) {
            asm volatile("cp.async.wait_group 1;" ::: "memory");
            __syncthreads();
            if (i + 2 < NCHUNK) { loadA(P, i + 2, s_load); loadB(P, i + 2, s_load); }
            asm volatile("cp.async.commit_group;" ::: "memory");

            uint32_t base = sb + (uint32_t)s_cmp * STAGE_BYTES;
            uint32_t a[2][2][4], bt[2][2][4];
            ldsm_ks(base, 0, a[0], bt[0]);
            #pragma unroll
            for (int ks = 0; ks < 8; ks++) {
                int cur = ks & 1;
                if (ks < 7) ldsm_ks(base, ks + 1, a[cur ^ 1], bt[cur ^ 1]);
                #pragma unroll
                for (int mi = 0; mi < 2; mi++)
                    #pragma unroll
                    for (int ni = 0; ni < 4; ni++)
                        mma_bf16(d[mi][ni][0], d[mi][ni][1], d[mi][ni][2], d[mi][ni][3],
                                 a[cur][mi][0], a[cur][mi][1], a[cur][mi][2], a[cur][mi][3],
                                 bt[cur][ni >> 1][(ni & 1) * 2], bt[cur][ni >> 1][(ni & 1) * 2 + 1]);
            }
            if (++s_cmp == 3) s_cmp = 0;
            if (++s_load == 3) s_load = 0;
        }

        asm volatile("cp.async.wait_group 0;" ::: "memory");
        __syncthreads();

        // stage accumulators: per-warp [32 rows][33 floats]
        float* st = (float*)(smem + (size_t)wid * 32 * 33 * 4);
        #pragma unroll
        for (int mi = 0; mi < 2; mi++) {
            int r0 = mi * 16 + (lane >> 2);
            #pragma unroll
            for (int ni = 0; ni < 4; ni++) {
                int c0 = ni * 8 + 2 * (lane & 3);
                st[r0 * 33 + c0]           = d[mi][ni][0];
                st[r0 * 33 + c0 + 1]       = d[mi][ni][1];
                st[(r0 + 8) * 33 + c0]     = d[mi][ni][2];
                st[(r0 + 8) * 33 + c0 + 1] = d[mi][ni][3];
            }
        }
        __syncwarp();

        // gate math
        {
            const float* zrow = st + lane * 33;
            const int m  = blockRow + wm * 32 + lane;
            const int ug = (blockN >> 2) + wn * 8;
            const float4* bq = (const float4*)(&g_biasp[j][blockN + wn * 32]);
            float* cp = &g_c[j][(size_t)m * HID + ug];
            float4 co0 = *(const float4*)(cp);
            float4 co1 = *(const float4*)(cp + 4);
            float cold[8] = {co0.x, co0.y, co0.z, co0.w, co1.x, co1.y, co1.z, co1.w};
            float cn[8], hn[8];
            #pragma unroll
            for (int k = 0; k < 8; k++) {
                float4 bb = bq[k];
                float zi = zrow[4 * k]     + bb.x;
                float zf = zrow[4 * k + 1] + bb.y;
                float zg = zrow[4 * k + 2] + bb.z;
                float zo = zrow[4 * k + 3] + bb.w;
                float ig = 1.0f / (1.0f + __expf(-zi));
                float fg = 1.0f / (1.0f + __expf(-zf));
                float gg = tanhf(zg);
                float og = 1.0f / (1.0f + __expf(-zo));
                float c_ = fg * cold[k] + ig * gg;
                cn[k] = c_;
                hn[k] = og * tanhf(c_);
            }
            *(float4*)(cp)     = make_float4(cn[0], cn[1], cn[2], cn[3]);
            *(float4*)(cp + 4) = make_float4(cn[4], cn[5], cn[6], cn[7]);

            uint32_t chi[8], clo[8], hhi[8], hlo[8];
            #pragma unroll
            for (int k = 0; k < 8; k++) {
                split_bf(cn[k], chi[k], clo[k]);
                split_bf(hn[k], hhi[k], hlo[k]);
            }
            size_t so = (size_t)m * HID + ug;
            __nv_bfloat16* curh_o = g_curh[(j + 1) & 1];
            __nv_bfloat16* curl_o = g_curl[(j + 1) & 1];
            __nv_bfloat16* hh_o   = g_hh[j][(t + 1) & 1];
            __nv_bfloat16* hl_o   = g_hl[j][(t + 1) & 1];
            uint4 v;
            v = make_uint4(chi[0] | (chi[1] << 16), chi[2] | (chi[3] << 16),
                           chi[4] | (chi[5] << 16), chi[6] | (chi[7] << 16));
            *(uint4*)(curh_o + so) = v;
            v = make_uint4(clo[0] | (clo[1] << 16), clo[2] | (clo[3] << 16),
                           clo[4] | (clo[5] << 16), clo[6] | (clo[7] << 16));
            *(uint4*)(curl_o + so) = v;
            v = make_uint4(hhi[0] | (hhi[1] << 16), hhi[2] | (hhi[3] << 16),
                           hhi[4] | (hhi[5] << 16), hhi[6] | (hhi[7] << 16));
            *(uint4*)(hh_o + so) = v;
            v = make_uint4(hlo[0] | (hlo[1] << 16), hlo[2] | (hlo[3] << 16),
                           hlo[4] | (hlo[5] << 16), hlo[6] | (hlo[7] << 16));
            *(uint4*)(hl_o + so) = v;

            if (step == NSTEPS - 1) {
                *(float4*)(out + so)     = make_float4(cn[0], cn[1], cn[2], cn[3]);
                *(float4*)(out + so + 4) = make_float4(cn[4], cn[5], cn[6], cn[7]);
            }
        }

        // -------- barrier + cross-step prefetch --------
        if (step < NSTEPS - 1) {
            __syncthreads();   // epilogue smem reads done before prefetch overwrites stages
            Ptrs Pn;
            get_ptrs(step + 1, Pn);
            // weights are state-independent: prefetch BEFORE the barrier
            loadB(Pn, 0, 0); asm volatile("cp.async.commit_group;" ::: "memory");
            loadB(Pn, 1, 1); asm volatile("cp.async.commit_group;" ::: "memory");
            if (tid == 0) {
                __threadfence();
                atomicAdd(&g_bar, 1u);
                unsigned target = (unsigned)(step + 1) * GRID_CTAS;
                unsigned v;
                do {
                    asm volatile("ld.acquire.gpu.global.u32 %0, [%1];" : "=r"(v) : "l"(&g_bar));
                } while (v < target);
            }
            __syncthreads();
            // activations depend on the step we just synced on
            loadA(Pn, 0, 0); asm volatile("cp.async.commit_group;" ::: "memory");
            loadA(Pn, 1, 1); asm volatile("cp.async.commit_group;" ::: "memory");
        }
    }
}

// ---------------- host launcher ----------------
extern "C" void kernel_launch(void* const* d_in, const int* in_sizes, int n_in,
                              void* d_out, int out_size)
{
    const float* inputs = (const float*)d_in[0];
    const float* kernel = (const float*)d_in[1];
    const float* rec    = (const float*)d_in[2];
    const float* bias   = (const float*)d_in[3];
    float* out = (float*)d_out;

    cudaFuncSetAttribute(lstm_persistent_kernel,
                         cudaFuncAttributeMaxDynamicSharedMemorySize, SMEM_BYTES);

    {
        int n = LAYERS * BH;
        zero_state_kernel<<<(n + 255) / 256, 256>>>();
        bias_perm_kernel<<<(LAYERS * ZCOLS + 255) / 256, 256>>>(bias);
        wsplit_kernel<<<dim3(ZCOLS / 32, HID / 32, 2 * LAYERS), dim3(32, 8)>>>(kernel, rec);
        xsplit_kernel<<<(T_STEPS * BH + 255) / 256, 256>>>(inputs);
    }

    dim3 grid(32, 4);   // 128 CTAs, all resident — required by the barrier
    lstm_persistent_kernel<<<grid, 256, SMEM_BYTES>>>(out);
}